// round 2
// baseline (speedup 1.0000x reference)
#include <cuda_runtime.h>
#include <math.h>

#define DIM   512
#define SEQ   257
#define DZR   6
#define DXA   5
#define LZR   (DZR*SEQ)      // 1542
#define LXA   (DXA*SEQ)      // 1285
#define LT    (LZR+LXA)      // 2827
#define NHEAD 8
#define DH    64
#define HIDN  2048
#define NBLK  6

// ---------------- static scratch (no allocation allowed) ----------------
__device__ float g_act [LT*DIM];
__device__ float g_cat [LT*DIM];
__device__ float g_q   [LT*DIM];
__device__ float g_k   [LT*DIM];
__device__ float g_v   [LT*DIM];
__device__ float g_attn[LT*DIM];
__device__ float g_h   [LT*DIM];
__device__ float g_u   [LT*2*HIDN];   // geglu pre-act / attn-proj temp
__device__ float g_ffv [LT*HIDN];
__device__ float g_ms1 [NBLK*7*2*DIM];
__device__ float g_ms2 [NBLK*7*2*DIM];
__device__ float g_gt1 [NBLK*7*DIM];
__device__ float g_gt2 [NBLK*7*DIM];

// ---------------- helpers ----------------
__device__ __forceinline__ void blockreduce2(float& s, float& s2) {
  #pragma unroll
  for (int off = 16; off; off >>= 1) {
    s  += __shfl_xor_sync(0xffffffffu, s,  off);
    s2 += __shfl_xor_sync(0xffffffffu, s2, off);
  }
  __shared__ float sh[8];
  int w = threadIdx.x >> 5;
  if ((threadIdx.x & 31) == 0) { sh[w] = s; sh[4 + w] = s2; }
  __syncthreads();
  s  = sh[0] + sh[1] + sh[2] + sh[3];
  s2 = sh[4] + sh[5] + sh[6] + sh[7];
}

// ---------------- token build: zr||xa -> g_act ----------------
__global__ void build_tokens(const float* __restrict__ z, const float* __restrict__ frames,
                             const int* __restrict__ actions,
                             const float* __restrict__ Wp, const float* __restrict__ bp,
                             const float* __restrict__ regs, const float* __restrict__ pe,
                             const float* __restrict__ aemb, float* __restrict__ act)
{
  const int row = blockIdx.x, t = threadIdx.x;  // 128 threads
  const bool is_zr = row < LZR;
  int fr, tok; const float* src;
  if (is_zr) { fr = row / SEQ; tok = row - fr*SEQ; src = z + fr*3*32*32; }
  else { int r2 = row - LZR; fr = r2 / SEQ; tok = r2 - fr*SEQ; src = frames + fr*3*32*32; }

  if (tok < 256) {
    __shared__ float feat[12];
    if (t < 12) {
      int c = t >> 2, py = (t >> 1) & 1, px = t & 1;
      int hp = tok >> 4, wp = tok & 15;
      feat[t] = src[(c*32 + hp*2 + py)*32 + wp*2 + px];
    }
    __syncthreads();
    #pragma unroll
    for (int i = 0; i < 4; i++) {
      int d = t + i*128;
      float s = bp[d] + pe[tok*DIM + d];
      #pragma unroll
      for (int k = 0; k < 12; k++) s += feat[k] * Wp[k*DIM + d];
      act[(size_t)row*DIM + d] = s;
    }
  } else {
    if (is_zr) {
      #pragma unroll
      for (int i = 0; i < 4; i++) { int d = t + i*128; act[(size_t)row*DIM + d] = regs[d]; }
    } else {
      int ai = actions[fr];
      #pragma unroll
      for (int i = 0; i < 4; i++) { int d = t + i*128; act[(size_t)row*DIM + d] = aemb[ai*DIM + d]; }
    }
  }
}

// ---------------- per-(block,slot) cond vectors ----------------
// slot 0..5 = noisy frames (time_emb[ts[f]]), slot 6 = clean (time_emb[0])
__global__ void precompute_cond(const int* __restrict__ ts, const float* __restrict__ temb,
                                const float* __restrict__ Wm1, const float* __restrict__ bm1,
                                const float* __restrict__ Wm2, const float* __restrict__ bm2,
                                const float* __restrict__ Wg1, const float* __restrict__ bg1,
                                const float* __restrict__ Wg2, const float* __restrict__ bg2)
{
  const int slot = blockIdx.x;   // 0..6
  const int blk  = blockIdx.y;   // 0..5
  const int t = threadIdx.x;     // 256
  __shared__ float c[DIM], sc[DIM];
  int tv = (slot < 6) ? ts[slot] : 0;
  for (int i = t; i < DIM; i += 256) {
    float v = temb[(size_t)tv*DIM + i];
    c[i]  = v;
    sc[i] = v / (1.f + __expf(-v));    // silu
  }
  __syncthreads();
  {
    const float* w = Wm1 + (size_t)blk*DIM*2*DIM;
    for (int o = t; o < 2*DIM; o += 256) {
      float s = bm1[blk*2*DIM + o];
      for (int d = 0; d < DIM; d++) s += sc[d] * w[(size_t)d*2*DIM + o];
      g_ms1[(blk*7 + slot)*2*DIM + o] = s;
    }
  }
  {
    const float* w = Wm2 + (size_t)blk*DIM*2*DIM;
    for (int o = t; o < 2*DIM; o += 256) {
      float s = bm2[blk*2*DIM + o];
      for (int d = 0; d < DIM; d++) s += sc[d] * w[(size_t)d*2*DIM + o];
      g_ms2[(blk*7 + slot)*2*DIM + o] = s;
    }
  }
  {
    const float* w = Wg1 + (size_t)blk*DIM*DIM;
    for (int o = t; o < DIM; o += 256) {
      float s = bg1[blk*DIM + o];
      for (int d = 0; d < DIM; d++) s += c[d] * w[(size_t)d*DIM + o];
      g_gt1[(blk*7 + slot)*DIM + o] = s;
    }
  }
  {
    const float* w = Wg2 + (size_t)blk*DIM*DIM;
    for (int o = t; o < DIM; o += 256) {
      float s = bg2[blk*DIM + o];
      for (int d = 0; d < DIM; d++) s += c[d] * w[(size_t)d*DIM + o];
      g_gt2[(blk*7 + slot)*DIM + o] = s;
    }
  }
}

// ---------------- AdaLN modulate: Y = LN(X)*(1+scale)+shift ----------------
__global__ void row_mod(const float* __restrict__ X, const float* __restrict__ ms,
                        float* __restrict__ Y)
{
  const int row = blockIdx.x, t = threadIdx.x;  // 128
  const int slot = (row < LZR) ? (row / SEQ) : 6;
  const float* mr = ms + slot*2*DIM;
  const float* x = X + (size_t)row*DIM;
  float v[4]; float s = 0.f, s2 = 0.f;
  #pragma unroll
  for (int i = 0; i < 4; i++) { v[i] = x[t + i*128]; s += v[i]; s2 += v[i]*v[i]; }
  blockreduce2(s, s2);
  float mean = s * (1.f/512.f);
  float var  = s2 * (1.f/512.f) - mean*mean;
  float rs = rsqrtf(var + 1e-5f);
  #pragma unroll
  for (int i = 0; i < 4; i++) {
    int d = t + i*128;
    Y[(size_t)row*DIM + d] = (v[i] - mean)*rs*(1.f + mr[d]) + mr[DIM + d];
  }
}

// ---------------- Y = LN(cat*g1 + attn)*(1+scale2)+shift2 ----------------
__global__ void gate_add_mod(const float* __restrict__ C, const float* __restrict__ A,
                             const float* __restrict__ gt, const float* __restrict__ ms,
                             float* __restrict__ Y)
{
  const int row = blockIdx.x, t = threadIdx.x;
  const int slot = (row < LZR) ? (row / SEQ) : 6;
  const float* g  = gt + slot*DIM;
  const float* mr = ms + slot*2*DIM;
  const float* c = C + (size_t)row*DIM;
  const float* a = A + (size_t)row*DIM;
  float v[4]; float s = 0.f, s2 = 0.f;
  #pragma unroll
  for (int i = 0; i < 4; i++) {
    int d = t + i*128;
    v[i] = c[d]*g[d] + a[d];
    s += v[i]; s2 += v[i]*v[i];
  }
  blockreduce2(s, s2);
  float mean = s * (1.f/512.f);
  float var  = s2 * (1.f/512.f) - mean*mean;
  float rs = rsqrtf(var + 1e-5f);
  #pragma unroll
  for (int i = 0; i < 4; i++) {
    int d = t + i*128;
    Y[(size_t)row*DIM + d] = (v[i] - mean)*rs*(1.f + mr[d]) + mr[DIM + d];
  }
}

// ---------------- generic tiled fp32 GEMM: C = A@W + bias ----------------
// A [M,K] row-major, W [K,N], N%64==0, K%16==0
__global__ void __launch_bounds__(256, 1)
gemm_bias(const float* __restrict__ A, const float* __restrict__ W,
          const float* __restrict__ bias, float* __restrict__ C,
          int M, int N, int K)
{
  __shared__ float As[16][64];
  __shared__ float Bs[16][64];
  const int t = threadIdx.x;           // 256
  const int tx = t & 15, ty = t >> 4;
  const int bm = blockIdx.y * 64, bn = blockIdx.x * 64;
  float acc[4][4];
  #pragma unroll
  for (int i = 0; i < 4; i++)
    #pragma unroll
    for (int j = 0; j < 4; j++) acc[i][j] = 0.f;

  const int arow = t >> 2, acol = (t & 3) * 4;
  const int brow = t >> 4, bcol = (t & 15) * 4;
  const bool aok = (bm + arow) < M;

  for (int k0 = 0; k0 < K; k0 += 16) {
    float4 av = make_float4(0.f, 0.f, 0.f, 0.f);
    if (aok) av = *(const float4*)(A + (size_t)(bm + arow)*K + k0 + acol);
    As[acol + 0][arow] = av.x; As[acol + 1][arow] = av.y;
    As[acol + 2][arow] = av.z; As[acol + 3][arow] = av.w;
    *(float4*)&Bs[brow][bcol] = *(const float4*)(W + (size_t)(k0 + brow)*N + bn + bcol);
    __syncthreads();
    #pragma unroll
    for (int kk = 0; kk < 16; kk++) {
      float4 a4 = *(const float4*)&As[kk][ty*4];
      float4 b4 = *(const float4*)&Bs[kk][tx*4];
      float ar[4] = {a4.x, a4.y, a4.z, a4.w};
      float br[4] = {b4.x, b4.y, b4.z, b4.w};
      #pragma unroll
      for (int i = 0; i < 4; i++)
        #pragma unroll
        for (int j = 0; j < 4; j++) acc[i][j] += ar[i]*br[j];
    }
    __syncthreads();
  }
  #pragma unroll
  for (int i = 0; i < 4; i++) {
    int r = bm + ty*4 + i;
    if (r < M) {
      float4 o;
      o.x = acc[i][0] + bias[bn + tx*4 + 0];
      o.y = acc[i][1] + bias[bn + tx*4 + 1];
      o.z = acc[i][2] + bias[bn + tx*4 + 2];
      o.w = acc[i][3] + bias[bn + tx*4 + 3];
      *(float4*)(C + (size_t)r*N + bn + tx*4) = o;
    }
  }
}

// ---------------- flash attention (block-sparse masks -> key ranges) ------
// mode 0: cross  (q = zr rows; keys: own zr frame + previous <=4 xa frames)
// mode 1: self   (q = xa rows; keys: xa frames <= own)
// grid: (qtile[3], frame, head), 128 threads, 1 query/thread
__global__ void __launch_bounds__(128, 1)
attn_kernel(const float* __restrict__ Q, const float* __restrict__ K,
            const float* __restrict__ V, float* __restrict__ O, int mode)
{
  const int tile = blockIdx.x, f = blockIdx.y, h = blockIdx.z;
  int qrow0, r0s, r0l, r1s, r1l;
  if (mode == 0) {
    qrow0 = f*SEQ + tile*128;
    r0s = f*SEQ; r0l = SEQ;
    int j0 = f - 4; if (j0 < 0) j0 = 0;
    r1s = LZR + j0*SEQ; r1l = (f - j0)*SEQ;
  } else {
    qrow0 = LZR + f*SEQ + tile*128;
    r0s = LZR; r0l = (f + 1)*SEQ;
    r1s = 0; r1l = 0;
  }
  int nq = SEQ - tile*128; if (nq > 128) nq = 128;
  const int t = threadIdx.x;
  const bool active = t < nq;
  const int qr = qrow0 + t;

  float q[64], o[64];
  #pragma unroll
  for (int d = 0; d < 64; d++) o[d] = 0.f;
  if (active) {
    const float4* qp = (const float4*)(Q + (size_t)qr*DIM + h*DH);
    #pragma unroll
    for (int i = 0; i < 16; i++) {
      float4 v4 = qp[i];
      q[4*i+0] = v4.x*0.125f; q[4*i+1] = v4.y*0.125f;
      q[4*i+2] = v4.z*0.125f; q[4*i+3] = v4.w*0.125f;
    }
  }
  float m = -1e30f, l = 0.f;
  __shared__ float Ks[64][64];
  __shared__ float Vs[64][64];

  for (int r = 0; r < 2; r++) {
    const int ks = r ? r1s : r0s;
    const int kl = r ? r1l : r0l;
    for (int k0 = 0; k0 < kl; k0 += 64) {
      const int tl = min(64, kl - k0);
      __syncthreads();
      #pragma unroll
      for (int it = 0; it < 8; it++) {
        int idx = it*128 + t;
        int j = idx >> 4, d4 = (idx & 15) * 4;
        if (j < tl) {
          *(float4*)&Ks[j][d4] = *(const float4*)(K + (size_t)(ks + k0 + j)*DIM + h*DH + d4);
          *(float4*)&Vs[j][d4] = *(const float4*)(V + (size_t)(ks + k0 + j)*DIM + h*DH + d4);
        }
      }
      __syncthreads();
      if (active) {
        for (int j = 0; j < tl; j++) {
          float s = 0.f;
          #pragma unroll
          for (int d = 0; d < 64; d += 4) {
            float4 k4 = *(const float4*)&Ks[j][d];
            s += q[d]*k4.x + q[d+1]*k4.y + q[d+2]*k4.z + q[d+3]*k4.w;
          }
          float mn   = fmaxf(m, s);
          float corr = __expf(m - mn);
          float p    = __expf(s - mn);
          l = l*corr + p;
          if (corr != 1.f) {
            #pragma unroll
            for (int d = 0; d < 64; d++) o[d] *= corr;
          }
          m = mn;
          #pragma unroll
          for (int d = 0; d < 64; d += 4) {
            float4 v4 = *(const float4*)&Vs[j][d];
            o[d] += p*v4.x; o[d+1] += p*v4.y; o[d+2] += p*v4.z; o[d+3] += p*v4.w;
          }
        }
      }
    }
  }
  if (active) {
    float inv = 1.f / l;
    float4* op = (float4*)(O + (size_t)qr*DIM + h*DH);
    #pragma unroll
    for (int i = 0; i < 16; i++) {
      float4 v4;
      v4.x = o[4*i+0]*inv; v4.y = o[4*i+1]*inv;
      v4.z = o[4*i+2]*inv; v4.w = o[4*i+3]*inv;
      op[i] = v4;
    }
  }
}

// ---------------- geglu elementwise: ffv = a * gelu(g) ----------------
__global__ void geglu_act(const float* __restrict__ u, float* __restrict__ out)
{
  int idx = blockIdx.x*256 + threadIdx.x;
  if (idx >= LT*HIDN) return;
  int row = idx / HIDN, j = idx - row*HIDN;
  float a = u[(size_t)row*2*HIDN + j];
  float g = u[(size_t)row*2*HIDN + HIDN + j];
  float ge = 0.5f * g * (1.f + erff(g * 0.70710678118654752f));
  out[idx] = a * ge;
}

// ---------------- gate2: act = ff * g2[slot] ----------------
__global__ void gate2k(const float* __restrict__ ff, const float* __restrict__ gt,
                       float* __restrict__ act)
{
  int idx = blockIdx.x*256 + threadIdx.x;
  if (idx >= LT*DIM) return;
  int row = idx / DIM, d = idx - row*DIM;
  int slot = (row < LZR) ? row/SEQ : 6;
  act[idx] = ff[idx] * gt[slot*DIM + d];
}

// ---------------- unpatch: out[1,6,3,32,32] ----------------
__global__ void unpatch(const float* __restrict__ act, const float* __restrict__ Wu,
                        const float* __restrict__ bu, float* __restrict__ out)
{
  int e = blockIdx.x*128 + threadIdx.x;
  if (e >= DZR*3*32*32) return;
  int f   = e / (3*32*32);
  int rem = e - f*3*32*32;
  int c = rem >> 10;
  int y = (rem >> 5) & 31;
  int x = rem & 31;
  int row = f*SEQ + (y >> 1)*16 + (x >> 1);
  int k = c*4 + (y & 1)*2 + (x & 1);
  float s = bu[k];
  const float* a = act + (size_t)row*DIM;
  for (int d = 0; d < DIM; d++) s += a[d]*Wu[d*12 + k];
  out[e] = s;
}

// ---------------- launch ----------------
extern "C" void kernel_launch(void* const* d_in, const int* in_sizes, int n_in,
                              void* d_out, int out_size)
{
  const float* z        = (const float*)d_in[0];
  const float* frames   = (const float*)d_in[1];
  const int*   actions  = (const int*)  d_in[2];
  const int*   ts       = (const int*)  d_in[3];
  const float* Wp       = (const float*)d_in[4];
  const float* bp       = (const float*)d_in[5];
  const float* Wu       = (const float*)d_in[6];
  const float* bu       = (const float*)d_in[7];
  const float* regs     = (const float*)d_in[8];
  const float* pe       = (const float*)d_in[9];
  const float* aemb     = (const float*)d_in[10];
  const float* temb     = (const float*)d_in[11];
  const float* Wm1      = (const float*)d_in[12];
  const float* bm1      = (const float*)d_in[13];
  const float* Wm2      = (const float*)d_in[14];
  const float* bm2      = (const float*)d_in[15];
  const float* Wq       = (const float*)d_in[16];
  const float* bq       = (const float*)d_in[17];
  const float* Wk       = (const float*)d_in[18];
  const float* bk       = (const float*)d_in[19];
  const float* Wv       = (const float*)d_in[20];
  const float* bv       = (const float*)d_in[21];
  const float* Wo       = (const float*)d_in[22];
  const float* bo       = (const float*)d_in[23];
  const float* Wg1      = (const float*)d_in[24];
  const float* bg1      = (const float*)d_in[25];
  const float* Wg2      = (const float*)d_in[26];
  const float* bg2      = (const float*)d_in[27];
  const float* Wgeglu   = (const float*)d_in[28];
  const float* bgeglu   = (const float*)d_in[29];
  const float* Wff      = (const float*)d_in[30];
  const float* bff      = (const float*)d_in[31];

  float *act, *cat, *q, *k, *v, *attn, *h, *u, *ffv, *ms1, *ms2, *gt1, *gt2;
  cudaGetSymbolAddress((void**)&act,  g_act);
  cudaGetSymbolAddress((void**)&cat,  g_cat);
  cudaGetSymbolAddress((void**)&q,    g_q);
  cudaGetSymbolAddress((void**)&k,    g_k);
  cudaGetSymbolAddress((void**)&v,    g_v);
  cudaGetSymbolAddress((void**)&attn, g_attn);
  cudaGetSymbolAddress((void**)&h,    g_h);
  cudaGetSymbolAddress((void**)&u,    g_u);
  cudaGetSymbolAddress((void**)&ffv,  g_ffv);
  cudaGetSymbolAddress((void**)&ms1,  g_ms1);
  cudaGetSymbolAddress((void**)&ms2,  g_ms2);
  cudaGetSymbolAddress((void**)&gt1,  g_gt1);
  cudaGetSymbolAddress((void**)&gt2,  g_gt2);

  const int MROWS = (LT + 63) / 64;

  build_tokens<<<LT, 128>>>(z, frames, actions, Wp, bp, regs, pe, aemb, act);
  precompute_cond<<<dim3(7, NBLK), 256>>>(ts, temb, Wm1, bm1, Wm2, bm2, Wg1, bg1, Wg2, bg2);

  for (int i = 0; i < NBLK; i++) {
    // zrn / xan = AdaLN-mod of current activations
    row_mod<<<LT, 128>>>(act, ms1 + i*7*2*DIM, cat);
    // Q,K,V over all 2827 rows (zrn || xan)
    gemm_bias<<<dim3(8, MROWS), 256>>>(cat, Wq + (size_t)i*DIM*DIM, bq + i*DIM, q, LT, DIM, DIM);
    gemm_bias<<<dim3(8, MROWS), 256>>>(cat, Wk + (size_t)i*DIM*DIM, bk + i*DIM, k, LT, DIM, DIM);
    gemm_bias<<<dim3(8, MROWS), 256>>>(cat, Wv + (size_t)i*DIM*DIM, bv + i*DIM, v, LT, DIM, DIM);
    // cross (zr queries) + self (xa queries)
    attn_kernel<<<dim3(3, DZR, NHEAD), 128>>>(q, k, v, attn, 0);
    attn_kernel<<<dim3(3, DXA, NHEAD), 128>>>(q, k, v, attn, 1);
    // output projection (temp into g_u)
    gemm_bias<<<dim3(8, MROWS), 256>>>(attn, Wo + (size_t)i*DIM*DIM, bo + i*DIM, u, LT, DIM, DIM);
    // h = LN(gate1(zrn/xan) + attn_proj) * (1+scale2) + shift2
    gate_add_mod<<<LT, 128>>>(cat, u, gt1 + i*7*DIM, ms2 + i*7*2*DIM, h);
    // GEGLU
    gemm_bias<<<dim3(64, MROWS), 256>>>(h, Wgeglu + (size_t)i*DIM*2*HIDN, bgeglu + i*2*HIDN, u, LT, 2*HIDN, DIM);
    geglu_act<<<(LT*HIDN + 255)/256, 256>>>(u, ffv);
    gemm_bias<<<dim3(8, MROWS), 256>>>(ffv, Wff + (size_t)i*HIDN*DIM, bff + i*DIM, cat, LT, DIM, HIDN);
    // gate2 -> next activations
    gate2k<<<(LT*DIM + 255)/256, 256>>>(cat, gt2 + i*7*DIM, act);
  }

  unpatch<<<(DZR*3*32*32 + 127)/128, 128>>>(act, Wu, bu, (float*)d_out);
}

// round 8
// speedup vs baseline: 1.4424x; 1.4424x over previous
#include <cuda_runtime.h>
#include <cuda_bf16.h>
#include <cstdint>
#include <math.h>

#define DIM   512
#define SEQ   257
#define DZR   6
#define DXA   5
#define LZR   (DZR*SEQ)      // 1542
#define LXA   (DXA*SEQ)      // 1285
#define LT    (LZR+LXA)      // 2827
#define NHEAD 8
#define DH    64
#define HIDN  2048
#define NBLK  6

// weight offsets inside the packed bf16 weight buffers
#define WQKVO_SZ   (NBLK*DIM*DIM)
#define OFF_Q      0
#define OFF_K      (1*WQKVO_SZ)
#define OFF_V      (2*WQKVO_SZ)
#define OFF_O      (3*WQKVO_SZ)
#define OFF_GEGLU  (4*WQKVO_SZ)
#define OFF_FF     (OFF_GEGLU + NBLK*DIM*2*HIDN)
#define WTOT       (OFF_FF + NBLK*HIDN*DIM)

// ---------------- static scratch (no allocation allowed) ----------------
__device__ float g_act [LT*DIM];
__device__ float g_cat [LT*DIM];
__device__ float g_q   [LT*DIM];
__device__ float g_k   [LT*DIM];
__device__ float g_v   [LT*DIM];
__device__ float g_attn[LT*DIM];
__device__ float g_h   [LT*DIM];
__device__ float g_u   [LT*2*HIDN];
__device__ float g_ffv [LT*HIDN];
__device__ float g_ms1 [NBLK*7*2*DIM];
__device__ float g_ms2 [NBLK*7*2*DIM];
__device__ float g_gt1 [NBLK*7*DIM];
__device__ float g_gt2 [NBLK*7*DIM];
// bf16 split buffers
__device__ __nv_bfloat16 g_bh[WTOT];
__device__ __nv_bfloat16 g_bl[WTOT];
__device__ __nv_bfloat16 g_xh[LT*HIDN];
__device__ __nv_bfloat16 g_xl[LT*HIDN];

// ---------------- device-side buffer selectors ----------------
__device__ __forceinline__ float* out_sel(int s) {
  switch (s) {
    case 0: return g_q;
    case 1: return g_k;
    case 2: return g_v;
    case 3: return g_u;
    default: return g_cat;
  }
}
__device__ __forceinline__ const float* src_sel(int s) {
  switch (s) {
    case 0: return g_cat;
    case 1: return g_attn;
    case 2: return g_h;
    default: return g_ffv;
  }
}

// ---------------- helpers ----------------
__device__ __forceinline__ uint32_t smem_u32(const void* p) {
  return (uint32_t)__cvta_generic_to_shared(p);
}
__device__ __forceinline__ void ldsm4(uint32_t* r, uint32_t a) {
  asm volatile("ldmatrix.sync.aligned.m8n8.x4.shared.b16 {%0,%1,%2,%3}, [%4];\n"
    : "=r"(r[0]), "=r"(r[1]), "=r"(r[2]), "=r"(r[3]) : "r"(a));
}
__device__ __forceinline__ void ldsm4t(uint32_t* r, uint32_t a) {
  asm volatile("ldmatrix.sync.aligned.m8n8.x4.trans.shared.b16 {%0,%1,%2,%3}, [%4];\n"
    : "=r"(r[0]), "=r"(r[1]), "=r"(r[2]), "=r"(r[3]) : "r"(a));
}
__device__ __forceinline__ void mma16816(float* d, const uint32_t* a, const uint32_t* b) {
  asm volatile("mma.sync.aligned.m16n8k16.row.col.f32.bf16.bf16.f32 "
    "{%0,%1,%2,%3}, {%4,%5,%6,%7}, {%8,%9}, {%0,%1,%2,%3};\n"
    : "+f"(d[0]), "+f"(d[1]), "+f"(d[2]), "+f"(d[3])
    : "r"(a[0]), "r"(a[1]), "r"(a[2]), "r"(a[3]), "r"(b[0]), "r"(b[1]));
}

__device__ __forceinline__ void blockreduce2(float& s, float& s2) {
  #pragma unroll
  for (int off = 16; off; off >>= 1) {
    s  += __shfl_xor_sync(0xffffffffu, s,  off);
    s2 += __shfl_xor_sync(0xffffffffu, s2, off);
  }
  __shared__ float sh[8];
  int w = threadIdx.x >> 5;
  if ((threadIdx.x & 31) == 0) { sh[w] = s; sh[4 + w] = s2; }
  __syncthreads();
  s  = sh[0] + sh[1] + sh[2] + sh[3];
  s2 = sh[4] + sh[5] + sh[6] + sh[7];
}

// ---------------- fp32 -> bf16 hi/lo split (weights) ----------------
__global__ void split_w(const float* __restrict__ X, long off, int n)
{
  int idx = blockIdx.x*256 + threadIdx.x;
  if (idx >= n) return;
  float v = X[idx];
  __nv_bfloat16 h = __float2bfloat16(v);
  g_bh[off + idx] = h;
  g_bl[off + idx] = __float2bfloat16(v - __bfloat162float(h));
}

// ---------------- fp32 -> bf16 hi/lo split (activations) ----------------
__global__ void split_x(int sel, int n)
{
  int idx = blockIdx.x*256 + threadIdx.x;
  if (idx >= n) return;
  const float* X = src_sel(sel);
  float v = X[idx];
  __nv_bfloat16 h = __float2bfloat16(v);
  g_xh[idx] = h;
  g_xl[idx] = __float2bfloat16(v - __bfloat162float(h));
}

// ---------------- token build: zr||xa -> g_act ----------------
__global__ void build_tokens(const float* __restrict__ z, const float* __restrict__ frames,
                             const int* __restrict__ actions,
                             const float* __restrict__ Wp, const float* __restrict__ bp,
                             const float* __restrict__ regs, const float* __restrict__ pe,
                             const float* __restrict__ aemb)
{
  const int row = blockIdx.x, t = threadIdx.x;  // 128 threads
  const bool is_zr = row < LZR;
  int fr, tok; const float* src;
  if (is_zr) { fr = row / SEQ; tok = row - fr*SEQ; src = z + fr*3*32*32; }
  else { int r2 = row - LZR; fr = r2 / SEQ; tok = r2 - fr*SEQ; src = frames + fr*3*32*32; }

  if (tok < 256) {
    __shared__ float feat[12];
    if (t < 12) {
      int c = t >> 2, py = (t >> 1) & 1, px = t & 1;
      int hp = tok >> 4, wp = tok & 15;
      feat[t] = src[(c*32 + hp*2 + py)*32 + wp*2 + px];
    }
    __syncthreads();
    #pragma unroll
    for (int i = 0; i < 4; i++) {
      int d = t + i*128;
      float s = bp[d] + pe[tok*DIM + d];
      #pragma unroll
      for (int k = 0; k < 12; k++) s += feat[k] * Wp[k*DIM + d];
      g_act[(size_t)row*DIM + d] = s;
    }
  } else {
    if (is_zr) {
      #pragma unroll
      for (int i = 0; i < 4; i++) { int d = t + i*128; g_act[(size_t)row*DIM + d] = regs[d]; }
    } else {
      int ai = actions[fr];
      #pragma unroll
      for (int i = 0; i < 4; i++) { int d = t + i*128; g_act[(size_t)row*DIM + d] = aemb[ai*DIM + d]; }
    }
  }
}

// ---------------- per-(block,slot) cond vectors, weight read once --------
// grid (12, NBLK). chunk 0-3: ms1(N=1024); 4-7: ms2; 8-9: gt1(N=512); 10-11: gt2
__global__ void precompute_cond2(const int* __restrict__ ts, const float* __restrict__ temb,
                                 const float* __restrict__ Wm1, const float* __restrict__ bm1,
                                 const float* __restrict__ Wm2, const float* __restrict__ bm2,
                                 const float* __restrict__ Wg1, const float* __restrict__ bg1,
                                 const float* __restrict__ Wg2, const float* __restrict__ bg2)
{
  __shared__ float c[7][DIM], sc[7][DIM];
  const int t = threadIdx.x;      // 256
  const int chunk = blockIdx.x, blk = blockIdx.y;
  for (int i = t; i < 7*DIM; i += 256) {
    int slot = i >> 9, d = i & 511;
    int tv = (slot < 6) ? ts[slot] : 0;
    float v = temb[(size_t)tv*DIM + d];
    c[slot][d]  = v;
    sc[slot][d] = v / (1.f + __expf(-v));
  }
  __syncthreads();

  float acc[7];
  if (chunk < 8) {
    const bool first = chunk < 4;
    const int o = ((chunk & 3)*256) + t;          // 0..1023
    const float* w  = (first ? Wm1 : Wm2) + (size_t)blk*DIM*2*DIM;
    const float* bb = (first ? bm1 : bm2);
    float* out = first ? g_ms1 : g_ms2;
    float b0 = bb[blk*2*DIM + o];
    #pragma unroll
    for (int s = 0; s < 7; s++) acc[s] = b0;
    for (int d = 0; d < DIM; d++) {
      float wv = w[(size_t)d*2*DIM + o];
      #pragma unroll
      for (int s = 0; s < 7; s++) acc[s] += sc[s][d] * wv;
    }
    #pragma unroll
    for (int s = 0; s < 7; s++) out[(blk*7 + s)*2*DIM + o] = acc[s];
  } else {
    const bool first = chunk < 10;
    const int o = ((chunk & 1)*256) + t;          // 0..511
    const float* w  = (first ? Wg1 : Wg2) + (size_t)blk*DIM*DIM;
    const float* bb = (first ? bg1 : bg2);
    float* out = first ? g_gt1 : g_gt2;
    float b0 = bb[blk*DIM + o];
    #pragma unroll
    for (int s = 0; s < 7; s++) acc[s] = b0;
    for (int d = 0; d < DIM; d++) {
      float wv = w[(size_t)d*DIM + o];
      #pragma unroll
      for (int s = 0; s < 7; s++) acc[s] += c[s][d] * wv;
    }
    #pragma unroll
    for (int s = 0; s < 7; s++) out[(blk*7 + s)*DIM + o] = acc[s];
  }
}

// ---------------- AdaLN modulate: g_cat = LN(g_act)*(1+scale)+shift -------
__global__ void row_mod(int blk)
{
  const int row = blockIdx.x, t = threadIdx.x;  // 128
  const int slot = (row < LZR) ? (row / SEQ) : 6;
  const float* mr = g_ms1 + (blk*7 + slot)*2*DIM;
  const float* x = g_act + (size_t)row*DIM;
  float v[4]; float s = 0.f, s2 = 0.f;
  #pragma unroll
  for (int i = 0; i < 4; i++) { v[i] = x[t + i*128]; s += v[i]; s2 += v[i]*v[i]; }
  blockreduce2(s, s2);
  float mean = s * (1.f/512.f);
  float var  = s2 * (1.f/512.f) - mean*mean;
  float rs = rsqrtf(var + 1e-5f);
  #pragma unroll
  for (int i = 0; i < 4; i++) {
    int d = t + i*128;
    g_cat[(size_t)row*DIM + d] = (v[i] - mean)*rs*(1.f + mr[d]) + mr[DIM + d];
  }
}

// ---------------- g_h = LN(g_cat*g1 + g_u)*(1+scale2)+shift2 ----------------
__global__ void gate_add_mod(int blk)
{
  const int row = blockIdx.x, t = threadIdx.x;
  const int slot = (row < LZR) ? (row / SEQ) : 6;
  const float* g  = g_gt1 + (blk*7 + slot)*DIM;
  const float* mr = g_ms2 + (blk*7 + slot)*2*DIM;
  const float* c = g_cat + (size_t)row*DIM;
  const float* a = g_u   + (size_t)row*DIM;
  float v[4]; float s = 0.f, s2 = 0.f;
  #pragma unroll
  for (int i = 0; i < 4; i++) {
    int d = t + i*128;
    v[i] = c[d]*g[d] + a[d];
    s += v[i]; s2 += v[i]*v[i];
  }
  blockreduce2(s, s2);
  float mean = s * (1.f/512.f);
  float var  = s2 * (1.f/512.f) - mean*mean;
  float rs = rsqrtf(var + 1e-5f);
  #pragma unroll
  for (int i = 0; i < 4; i++) {
    int d = t + i*128;
    g_h[(size_t)row*DIM + d] = (v[i] - mean)*rs*(1.f + mr[d]) + mr[DIM + d];
  }
}

// ---------------- split-bf16 tensor-core GEMM ----------------
// A = g_xh/g_xl [M,K] bf16 row-major; W = g_bh/g_bl + wOff [K,N]; C fp32.
#define BMT 128
#define BNT 64
#define BKT 32
__global__ void __launch_bounds__(256, 2)
gemm_mma(long wOff, const float* __restrict__ bias, int outSel,
         int M, int N, int K)
{
  __shared__ __align__(16) __nv_bfloat16 sAh[BMT][40];
  __shared__ __align__(16) __nv_bfloat16 sAl[BMT][40];
  __shared__ __align__(16) __nv_bfloat16 sBh[BKT][72];
  __shared__ __align__(16) __nv_bfloat16 sBl[BKT][72];
  const __nv_bfloat16* Ah = g_xh;
  const __nv_bfloat16* Al = g_xl;
  const __nv_bfloat16* Wh = g_bh + wOff;
  const __nv_bfloat16* Wl = g_bl + wOff;
  float* C = out_sel(outSel);

  const int t = threadIdx.x, lane = t & 31, wid = t >> 5;
  const int wm = wid >> 1, wn = wid & 1;               // 4 x 2 warp grid
  const int bm = blockIdx.y * BMT, bn = blockIdx.x * BNT;

  float acc[2][4][4];
  #pragma unroll
  for (int a = 0; a < 2; a++)
    #pragma unroll
    for (int b = 0; b < 4; b++)
      #pragma unroll
      for (int e = 0; e < 4; e++) acc[a][b][e] = 0.f;

  for (int k0 = 0; k0 < K; k0 += BKT) {
    #pragma unroll
    for (int i = 0; i < 2; i++) {             // A tile: 128x32
      int u = t + i*256;
      int r = u >> 2, c8 = (u & 3) << 3;
      int gr = bm + r;
      uint4 vh = make_uint4(0,0,0,0), vl = make_uint4(0,0,0,0);
      if (gr < M) {
        vh = *(const uint4*)(Ah + (size_t)gr*K + k0 + c8);
        vl = *(const uint4*)(Al + (size_t)gr*K + k0 + c8);
      }
      *(uint4*)&sAh[r][c8] = vh;
      *(uint4*)&sAl[r][c8] = vl;
    }
    {                                          // B tile: 32x64
      int r = t >> 3, c8 = (t & 7) << 3;
      *(uint4*)&sBh[r][c8] = *(const uint4*)(Wh + (size_t)(k0 + r)*N + bn + c8);
      *(uint4*)&sBl[r][c8] = *(const uint4*)(Wl + (size_t)(k0 + r)*N + bn + c8);
    }
    __syncthreads();
    #pragma unroll
    for (int ks = 0; ks < BKT; ks += 16) {
      uint32_t ah[2][4], al[2][4], bh[4][2], bl[4][2];
      #pragma unroll
      for (int mg = 0; mg < 2; mg++) {
        int row = wm*32 + mg*16 + (lane & 15);
        int col = ks + ((lane >> 4) << 3);
        ldsm4(ah[mg], smem_u32(&sAh[row][col]));
        ldsm4(al[mg], smem_u32(&sAl[row][col]));
      }
      #pragma unroll
      for (int h2 = 0; h2 < 2; h2++) {
        int row = ks + (lane & 15);
        int col = wn*32 + h2*16 + ((lane >> 4) << 3);
        uint32_t r4[4];
        ldsm4t(r4, smem_u32(&sBh[row][col]));
        bh[h2*2][0] = r4[0]; bh[h2*2][1] = r4[1];
        bh[h2*2+1][0] = r4[2]; bh[h2*2+1][1] = r4[3];
        ldsm4t(r4, smem_u32(&sBl[row][col]));
        bl[h2*2][0] = r4[0]; bl[h2*2][1] = r4[1];
        bl[h2*2+1][0] = r4[2]; bl[h2*2+1][1] = r4[3];
      }
      #pragma unroll
      for (int mg = 0; mg < 2; mg++)
        #pragma unroll
        for (int ng = 0; ng < 4; ng++) {
          mma16816(acc[mg][ng], ah[mg], bh[ng]);
          mma16816(acc[mg][ng], ah[mg], bl[ng]);
          mma16816(acc[mg][ng], al[mg], bh[ng]);
        }
    }
    __syncthreads();
  }
  #pragma unroll
  for (int mg = 0; mg < 2; mg++) {
    int r0 = bm + wm*32 + mg*16 + (lane >> 2);
    #pragma unroll
    for (int ng = 0; ng < 4; ng++) {
      int cc = bn + wn*32 + ng*8 + ((lane & 3) << 1);
      float b0 = bias[cc], b1 = bias[cc+1];
      if (r0 < M) {
        float2 o = make_float2(acc[mg][ng][0] + b0, acc[mg][ng][1] + b1);
        *(float2*)(C + (size_t)r0*N + cc) = o;
      }
      int r1 = r0 + 8;
      if (r1 < M) {
        float2 o = make_float2(acc[mg][ng][2] + b0, acc[mg][ng][3] + b1);
        *(float2*)(C + (size_t)r1*N + cc) = o;
      }
    }
  }
}

// ---------------- flash attention (block-sparse masks -> key ranges) ------
// mode 0: cross (zr queries), mode 1: self (xa queries). g_q/g_k/g_v -> g_attn
__global__ void __launch_bounds__(128, 1)
attn_kernel(int mode)
{
  const int tile = blockIdx.x, f = blockIdx.y, h = blockIdx.z;
  int qrow0, r0s, r0l, r1s, r1l;
  if (mode == 0) {
    qrow0 = f*SEQ + tile*128;
    r0s = f*SEQ; r0l = SEQ;
    int j0 = f - 4; if (j0 < 0) j0 = 0;
    r1s = LZR + j0*SEQ; r1l = (f - j0)*SEQ;
  } else {
    qrow0 = LZR + f*SEQ + tile*128;
    r0s = LZR; r0l = (f + 1)*SEQ;
    r1s = 0; r1l = 0;
  }
  int nq = SEQ - tile*128; if (nq > 128) nq = 128;
  const int t = threadIdx.x;
  const bool active = t < nq;
  const int qr = qrow0 + t;

  float q[64], o[64];
  #pragma unroll
  for (int d = 0; d < 64; d++) o[d] = 0.f;
  if (active) {
    const float4* qp = (const float4*)(g_q + (size_t)qr*DIM + h*DH);
    #pragma unroll
    for (int i = 0; i < 16; i++) {
      float4 v4 = qp[i];
      q[4*i+0] = v4.x*0.125f; q[4*i+1] = v4.y*0.125f;
      q[4*i+2] = v4.z*0.125f; q[4*i+3] = v4.w*0.125f;
    }
  }
  float m = -1e30f, l = 0.f;
  __shared__ float Ks[64][64];
  __shared__ float Vs[64][64];

  for (int r = 0; r < 2; r++) {
    const int ks = r ? r1s : r0s;
    const int kl = r ? r1l : r0l;
    for (int k0 = 0; k0 < kl; k0 += 64) {
      const int tl = min(64, kl - k0);
      __syncthreads();
      #pragma unroll
      for (int it = 0; it < 8; it++) {
        int idx = it*128 + t;
        int j = idx >> 4, d4 = (idx & 15) * 4;
        if (j < tl) {
          *(float4*)&Ks[j][d4] = *(const float4*)(g_k + (size_t)(ks + k0 + j)*DIM + h*DH + d4);
          *(float4*)&Vs[j][d4] = *(const float4*)(g_v + (size_t)(ks + k0 + j)*DIM + h*DH + d4);
        }
      }
      __syncthreads();
      if (active) {
        for (int j = 0; j < tl; j++) {
          float s = 0.f;
          #pragma unroll
          for (int d = 0; d < 64; d += 4) {
            float4 k4 = *(const float4*)&Ks[j][d];
            s += q[d]*k4.x + q[d+1]*k4.y + q[d+2]*k4.z + q[d+3]*k4.w;
          }
          float mn   = fmaxf(m, s);
          float corr = __expf(m - mn);
          float p    = __expf(s - mn);
          l = l*corr + p;
          if (corr != 1.f) {
            #pragma unroll
            for (int d = 0; d < 64; d++) o[d] *= corr;
          }
          m = mn;
          #pragma unroll
          for (int d = 0; d < 64; d += 4) {
            float4 v4 = *(const float4*)&Vs[j][d];
            o[d] += p*v4.x; o[d+1] += p*v4.y; o[d+2] += p*v4.z; o[d+3] += p*v4.w;
          }
        }
      }
    }
  }
  if (active) {
    float inv = 1.f / l;
    float4* op = (float4*)(g_attn + (size_t)qr*DIM + h*DH);
    #pragma unroll
    for (int i = 0; i < 16; i++) {
      float4 v4;
      v4.x = o[4*i+0]*inv; v4.y = o[4*i+1]*inv;
      v4.z = o[4*i+2]*inv; v4.w = o[4*i+3]*inv;
      op[i] = v4;
    }
  }
}

// ---------------- geglu elementwise: g_ffv = a * gelu(g) ----------------
__global__ void geglu_act()
{
  int idx = blockIdx.x*256 + threadIdx.x;
  if (idx >= LT*HIDN) return;
  int row = idx / HIDN, j = idx - row*HIDN;
  float a = g_u[(size_t)row*2*HIDN + j];
  float g = g_u[(size_t)row*2*HIDN + HIDN + j];
  float ge = 0.5f * g * (1.f + erff(g * 0.70710678118654752f));
  g_ffv[idx] = a * ge;
}

// ---------------- gate2: g_act = g_cat * g2[slot] ----------------
__global__ void gate2k(int blk)
{
  int idx = blockIdx.x*256 + threadIdx.x;
  if (idx >= LT*DIM) return;
  int row = idx / DIM, d = idx - row*DIM;
  int slot = (row < LZR) ? row/SEQ : 6;
  g_act[idx] = g_cat[idx] * g_gt2[(blk*7 + slot)*DIM + d];
}

// ---------------- unpatch: out[1,6,3,32,32] ----------------
__global__ void unpatch(const float* __restrict__ Wu, const float* __restrict__ bu,
                        float* __restrict__ out)
{
  int e = blockIdx.x*128 + threadIdx.x;
  if (e >= DZR*3*32*32) return;
  int f   = e / (3*32*32);
  int rem = e - f*3*32*32;
  int c = rem >> 10;
  int y = (rem >> 5) & 31;
  int x = rem & 31;
  int row = f*SEQ + (y >> 1)*16 + (x >> 1);
  int k = c*4 + (y & 1)*2 + (x & 1);
  float s = bu[k];
  const float* a = g_act + (size_t)row*DIM;
  for (int d = 0; d < DIM; d++) s += a[d]*Wu[d*12 + k];
  out[e] = s;
}

// ---------------- launch ----------------
extern "C" void kernel_launch(void* const* d_in, const int* in_sizes, int n_in,
                              void* d_out, int out_size)
{
  const float* z        = (const float*)d_in[0];
  const float* frames   = (const float*)d_in[1];
  const int*   actions  = (const int*)  d_in[2];
  const int*   ts       = (const int*)  d_in[3];
  const float* Wp       = (const float*)d_in[4];
  const float* bp       = (const float*)d_in[5];
  const float* Wu       = (const float*)d_in[6];
  const float* bu       = (const float*)d_in[7];
  const float* regs     = (const float*)d_in[8];
  const float* pe       = (const float*)d_in[9];
  const float* aemb     = (const float*)d_in[10];
  const float* temb     = (const float*)d_in[11];
  const float* Wm1      = (const float*)d_in[12];
  const float* bm1      = (const float*)d_in[13];
  const float* Wm2      = (const float*)d_in[14];
  const float* bm2      = (const float*)d_in[15];
  const float* Wq       = (const float*)d_in[16];
  const float* bq       = (const float*)d_in[17];
  const float* Wk       = (const float*)d_in[18];
  const float* bk       = (const float*)d_in[19];
  const float* Wv       = (const float*)d_in[20];
  const float* bv       = (const float*)d_in[21];
  const float* Wo       = (const float*)d_in[22];
  const float* bo       = (const float*)d_in[23];
  const float* Wg1      = (const float*)d_in[24];
  const float* bg1      = (const float*)d_in[25];
  const float* Wg2      = (const float*)d_in[26];
  const float* bg2      = (const float*)d_in[27];
  const float* Wgeglu   = (const float*)d_in[28];
  const float* bgeglu   = (const float*)d_in[29];
  const float* Wff      = (const float*)d_in[30];
  const float* bff      = (const float*)d_in[31];

  const int MT = (LT + BMT - 1) / BMT;   // 23 M-tiles

  build_tokens<<<LT, 128>>>(z, frames, actions, Wp, bp, regs, pe, aemb);
  precompute_cond2<<<dim3(12, NBLK), 256>>>(ts, temb, Wm1, bm1, Wm2, bm2, Wg1, bg1, Wg2, bg2);

  // one-time weight splits (inside graph)
  split_w<<<(WQKVO_SZ + 255)/256, 256>>>(Wq, OFF_Q, WQKVO_SZ);
  split_w<<<(WQKVO_SZ + 255)/256, 256>>>(Wk, OFF_K, WQKVO_SZ);
  split_w<<<(WQKVO_SZ + 255)/256, 256>>>(Wv, OFF_V, WQKVO_SZ);
  split_w<<<(WQKVO_SZ + 255)/256, 256>>>(Wo, OFF_O, WQKVO_SZ);
  split_w<<<(NBLK*DIM*2*HIDN + 255)/256, 256>>>(Wgeglu, OFF_GEGLU, NBLK*DIM*2*HIDN);
  split_w<<<(NBLK*HIDN*DIM + 255)/256, 256>>>(Wff, OFF_FF, NBLK*HIDN*DIM);

  for (int i = 0; i < NBLK; i++) {
    const long wo = (long)i*DIM*DIM;
    row_mod<<<LT, 128>>>(i);
    split_x<<<(LT*DIM + 255)/256, 256>>>(0, LT*DIM);   // from g_cat
    gemm_mma<<<dim3(8, MT), 256>>>(OFF_Q + wo, bq + i*DIM, 0, LT, DIM, DIM);
    gemm_mma<<<dim3(8, MT), 256>>>(OFF_K + wo, bk + i*DIM, 1, LT, DIM, DIM);
    gemm_mma<<<dim3(8, MT), 256>>>(OFF_V + wo, bv + i*DIM, 2, LT, DIM, DIM);
    attn_kernel<<<dim3(3, DZR, NHEAD), 128>>>(0);
    attn_kernel<<<dim3(3, DXA, NHEAD), 128>>>(1);
    split_x<<<(LT*DIM + 255)/256, 256>>>(1, LT*DIM);   // from g_attn
    gemm_mma<<<dim3(8, MT), 256>>>(OFF_O + wo, bo + i*DIM, 3, LT, DIM, DIM);
    gate_add_mod<<<LT, 128>>>(i);
    split_x<<<(LT*DIM + 255)/256, 256>>>(2, LT*DIM);   // from g_h
    gemm_mma<<<dim3(64, MT), 256>>>(OFF_GEGLU + (long)i*DIM*2*HIDN,
                                    bgeglu + i*2*HIDN, 3, LT, 2*HIDN, DIM);
    geglu_act<<<(LT*HIDN + 255)/256, 256>>>();
    split_x<<<(LT*HIDN + 255)/256, 256>>>(3, LT*HIDN); // from g_ffv
    gemm_mma<<<dim3(8, MT), 256>>>(OFF_FF + (long)i*HIDN*DIM,
                                   bff + i*DIM, 4, LT, DIM, HIDN);
    gate2k<<<(LT*DIM + 255)/256, 256>>>(i);
  }

  unpatch<<<(DZR*3*32*32 + 127)/128, 128>>>(Wu, bu, (float*)d_out);
}

// round 9
// speedup vs baseline: 1.5303x; 1.0609x over previous
#include <cuda_runtime.h>
#include <cuda_bf16.h>
#include <cstdint>
#include <math.h>

#define DIM   512
#define SEQ   257
#define DZR   6
#define DXA   5
#define LZR   (DZR*SEQ)      // 1542
#define LXA   (DXA*SEQ)      // 1285
#define LT    (LZR+LXA)      // 2827
#define NHEAD 8
#define DH    64
#define HIDN  2048
#define NBLK  6

// packed bf16 weight buffer offsets
#define QKV_N      1536
#define SZ_QKV     (NBLK*DIM*QKV_N)
#define SZ_O       (NBLK*DIM*DIM)
#define SZ_GEGLU   (NBLK*DIM*2*HIDN)
#define SZ_FF      (NBLK*HIDN*DIM)
#define OFF_QKV    0
#define OFF_O      (OFF_QKV + SZ_QKV)
#define OFF_GEGLU  (OFF_O + SZ_O)
#define OFF_FF     (OFF_GEGLU + SZ_GEGLU)
#define WTOT       (OFF_FF + SZ_FF)

// ---------------- static scratch (no allocation allowed) ----------------
__device__ float g_act [LT*DIM];
__device__ float g_cat [LT*DIM];
__device__ float g_qkv [LT*QKV_N];
__device__ float g_u   [LT*2*HIDN];
__device__ float g_ms1 [NBLK*7*2*DIM];
__device__ float g_ms2 [NBLK*7*2*DIM];
__device__ float g_gt1 [NBLK*7*DIM];
__device__ float g_gt2 [NBLK*7*DIM];
__device__ float g_bqkv[NBLK*QKV_N];
// bf16 split buffers
__device__ __nv_bfloat16 g_bh[WTOT];
__device__ __nv_bfloat16 g_bl[WTOT];
__device__ __nv_bfloat16 g_xh[LT*HIDN];
__device__ __nv_bfloat16 g_xl[LT*HIDN];

__device__ __forceinline__ float* out_sel(int s) {
  switch (s) {
    case 0: return g_qkv;
    case 1: return g_u;
    default: return g_cat;
  }
}

// ---------------- helpers ----------------
__device__ __forceinline__ uint32_t smem_u32(const void* p) {
  return (uint32_t)__cvta_generic_to_shared(p);
}
__device__ __forceinline__ void ldsm4(uint32_t* r, uint32_t a) {
  asm volatile("ldmatrix.sync.aligned.m8n8.x4.shared.b16 {%0,%1,%2,%3}, [%4];\n"
    : "=r"(r[0]), "=r"(r[1]), "=r"(r[2]), "=r"(r[3]) : "r"(a));
}
__device__ __forceinline__ void ldsm4t(uint32_t* r, uint32_t a) {
  asm volatile("ldmatrix.sync.aligned.m8n8.x4.trans.shared.b16 {%0,%1,%2,%3}, [%4];\n"
    : "=r"(r[0]), "=r"(r[1]), "=r"(r[2]), "=r"(r[3]) : "r"(a));
}
__device__ __forceinline__ void mma16816(float* d, const uint32_t* a, const uint32_t* b) {
  asm volatile("mma.sync.aligned.m16n8k16.row.col.f32.bf16.bf16.f32 "
    "{%0,%1,%2,%3}, {%4,%5,%6,%7}, {%8,%9}, {%0,%1,%2,%3};\n"
    : "+f"(d[0]), "+f"(d[1]), "+f"(d[2]), "+f"(d[3])
    : "r"(a[0]), "r"(a[1]), "r"(a[2]), "r"(a[3]), "r"(b[0]), "r"(b[1]));
}
__device__ __forceinline__ void cp16(uint32_t saddr, const void* g, bool ok) {
  int sz = ok ? 16 : 0;
  asm volatile("cp.async.cg.shared.global [%0], [%1], 16, %2;\n"
    :: "r"(saddr), "l"(g), "r"(sz));
}
__device__ __forceinline__ void cp_commit() { asm volatile("cp.async.commit_group;\n"); }
template<int N> __device__ __forceinline__ void cp_wait() {
  asm volatile("cp.async.wait_group %0;\n" :: "n"(N));
}

__device__ __forceinline__ void blockreduce2(float& s, float& s2) {
  #pragma unroll
  for (int off = 16; off; off >>= 1) {
    s  += __shfl_xor_sync(0xffffffffu, s,  off);
    s2 += __shfl_xor_sync(0xffffffffu, s2, off);
  }
  __shared__ float sh[8];
  int w = threadIdx.x >> 5;
  if ((threadIdx.x & 31) == 0) { sh[w] = s; sh[4 + w] = s2; }
  __syncthreads();
  s  = sh[0] + sh[1] + sh[2] + sh[3];
  s2 = sh[4] + sh[5] + sh[6] + sh[7];
}

__device__ __forceinline__ void store_split(size_t idx, float v) {
  __nv_bfloat16 h = __float2bfloat16(v);
  g_xh[idx] = h;
  g_xl[idx] = __float2bfloat16(v - __bfloat162float(h));
}

// ---------------- weight splits ----------------
__global__ void split_w(const float* __restrict__ X, long off, int n)
{
  int idx = blockIdx.x*256 + threadIdx.x;
  if (idx >= n) return;
  float v = X[idx];
  __nv_bfloat16 h = __float2bfloat16(v);
  g_bh[off + idx] = h;
  g_bl[off + idx] = __float2bfloat16(v - __bfloat162float(h));
}

// QKV packed: per block i, [K=512 rows, N=1536] with cols 0-511=Q,512-1023=K,1024-1535=V
__global__ void split_w_qkv(const float* __restrict__ Wq, const float* __restrict__ Wk,
                            const float* __restrict__ Wv)
{
  int idx = blockIdx.x*256 + threadIdx.x;
  if (idx >= SZ_QKV) return;
  int blk = idx / (DIM*QKV_N);
  int rem = idx - blk*(DIM*QKV_N);
  int r = rem / QKV_N, c = rem - r*QKV_N;
  const float* W = (c < DIM) ? Wq : ((c < 2*DIM) ? Wk : Wv);
  int cc = c & (DIM-1);
  float v = W[((size_t)blk*DIM + r)*DIM + cc];
  __nv_bfloat16 h = __float2bfloat16(v);
  g_bh[OFF_QKV + idx] = h;
  g_bl[OFF_QKV + idx] = __float2bfloat16(v - __bfloat162float(h));
}

__global__ void pack_bqkv(const float* __restrict__ bq, const float* __restrict__ bk,
                          const float* __restrict__ bv)
{
  int idx = blockIdx.x*256 + threadIdx.x;
  if (idx >= NBLK*QKV_N) return;
  int blk = idx / QKV_N, c = idx - blk*QKV_N;
  const float* b = (c < DIM) ? bq : ((c < 2*DIM) ? bk : bv);
  g_bqkv[idx] = b[blk*DIM + (c & (DIM-1))];
}

// ---------------- token build ----------------
__global__ void build_tokens(const float* __restrict__ z, const float* __restrict__ frames,
                             const int* __restrict__ actions,
                             const float* __restrict__ Wp, const float* __restrict__ bp,
                             const float* __restrict__ regs, const float* __restrict__ pe,
                             const float* __restrict__ aemb)
{
  const int row = blockIdx.x, t = threadIdx.x;  // 128 threads
  const bool is_zr = row < LZR;
  int fr, tok; const float* src;
  if (is_zr) { fr = row / SEQ; tok = row - fr*SEQ; src = z + fr*3*32*32; }
  else { int r2 = row - LZR; fr = r2 / SEQ; tok = r2 - fr*SEQ; src = frames + fr*3*32*32; }

  if (tok < 256) {
    __shared__ float feat[12];
    if (t < 12) {
      int c = t >> 2, py = (t >> 1) & 1, px = t & 1;
      int hp = tok >> 4, wp = tok & 15;
      feat[t] = src[(c*32 + hp*2 + py)*32 + wp*2 + px];
    }
    __syncthreads();
    #pragma unroll
    for (int i = 0; i < 4; i++) {
      int d = t + i*128;
      float s = bp[d] + pe[tok*DIM + d];
      #pragma unroll
      for (int k = 0; k < 12; k++) s += feat[k] * Wp[k*DIM + d];
      g_act[(size_t)row*DIM + d] = s;
    }
  } else {
    if (is_zr) {
      #pragma unroll
      for (int i = 0; i < 4; i++) { int d = t + i*128; g_act[(size_t)row*DIM + d] = regs[d]; }
    } else {
      int ai = actions[fr];
      #pragma unroll
      for (int i = 0; i < 4; i++) { int d = t + i*128; g_act[(size_t)row*DIM + d] = aemb[ai*DIM + d]; }
    }
  }
}

// ---------------- cond vectors, each weight matrix streamed once ----------
__global__ void precompute_cond2(const int* __restrict__ ts, const float* __restrict__ temb,
                                 const float* __restrict__ Wm1, const float* __restrict__ bm1,
                                 const float* __restrict__ Wm2, const float* __restrict__ bm2,
                                 const float* __restrict__ Wg1, const float* __restrict__ bg1,
                                 const float* __restrict__ Wg2, const float* __restrict__ bg2)
{
  __shared__ float c[7][DIM], sc[7][DIM];
  const int t = threadIdx.x;      // 256
  const int chunk = blockIdx.x, blk = blockIdx.y;
  for (int i = t; i < 7*DIM; i += 256) {
    int slot = i >> 9, d = i & 511;
    int tv = (slot < 6) ? ts[slot] : 0;
    float v = temb[(size_t)tv*DIM + d];
    c[slot][d]  = v;
    sc[slot][d] = v / (1.f + __expf(-v));
  }
  __syncthreads();

  float acc[7];
  if (chunk < 8) {
    const bool first = chunk < 4;
    const int o = ((chunk & 3)*256) + t;          // 0..1023
    const float* w  = (first ? Wm1 : Wm2) + (size_t)blk*DIM*2*DIM;
    const float* bb = (first ? bm1 : bm2);
    float* out = first ? g_ms1 : g_ms2;
    float b0 = bb[blk*2*DIM + o];
    #pragma unroll
    for (int s = 0; s < 7; s++) acc[s] = b0;
    for (int d = 0; d < DIM; d++) {
      float wv = w[(size_t)d*2*DIM + o];
      #pragma unroll
      for (int s = 0; s < 7; s++) acc[s] += sc[s][d] * wv;
    }
    #pragma unroll
    for (int s = 0; s < 7; s++) out[(blk*7 + s)*2*DIM + o] = acc[s];
  } else {
    const bool first = chunk < 10;
    const int o = ((chunk & 1)*256) + t;          // 0..511
    const float* w  = (first ? Wg1 : Wg2) + (size_t)blk*DIM*DIM;
    const float* bb = (first ? bg1 : bg2);
    float* out = first ? g_gt1 : g_gt2;
    float b0 = bb[blk*DIM + o];
    #pragma unroll
    for (int s = 0; s < 7; s++) acc[s] = b0;
    for (int d = 0; d < DIM; d++) {
      float wv = w[(size_t)d*DIM + o];
      #pragma unroll
      for (int s = 0; s < 7; s++) acc[s] += c[s][d] * wv;
    }
    #pragma unroll
    for (int s = 0; s < 7; s++) out[(blk*7 + s)*DIM + o] = acc[s];
  }
}

// ---------------- AdaLN modulate -> g_cat (fp32) + xh/xl (bf16) -----------
__global__ void row_mod(int blk)
{
  const int row = blockIdx.x, t = threadIdx.x;  // 128
  const int slot = (row < LZR) ? (row / SEQ) : 6;
  const float* mr = g_ms1 + (blk*7 + slot)*2*DIM;
  const float* x = g_act + (size_t)row*DIM;
  float v[4]; float s = 0.f, s2 = 0.f;
  #pragma unroll
  for (int i = 0; i < 4; i++) { v[i] = x[t + i*128]; s += v[i]; s2 += v[i]*v[i]; }
  blockreduce2(s, s2);
  float mean = s * (1.f/512.f);
  float var  = s2 * (1.f/512.f) - mean*mean;
  float rs = rsqrtf(var + 1e-5f);
  #pragma unroll
  for (int i = 0; i < 4; i++) {
    int d = t + i*128;
    float y = (v[i] - mean)*rs*(1.f + mr[d]) + mr[DIM + d];
    g_cat[(size_t)row*DIM + d] = y;
    store_split((size_t)row*DIM + d, y);
  }
}

// ---------------- xh/xl = LN(g_cat*g1 + g_u)*(1+scale2)+shift2 ------------
__global__ void gate_add_mod(int blk)
{
  const int row = blockIdx.x, t = threadIdx.x;
  const int slot = (row < LZR) ? (row / SEQ) : 6;
  const float* g  = g_gt1 + (blk*7 + slot)*DIM;
  const float* mr = g_ms2 + (blk*7 + slot)*2*DIM;
  const float* c = g_cat + (size_t)row*DIM;
  const float* a = g_u   + (size_t)row*DIM;
  float v[4]; float s = 0.f, s2 = 0.f;
  #pragma unroll
  for (int i = 0; i < 4; i++) {
    int d = t + i*128;
    v[i] = c[d]*g[d] + a[d];
    s += v[i]; s2 += v[i]*v[i];
  }
  blockreduce2(s, s2);
  float mean = s * (1.f/512.f);
  float var  = s2 * (1.f/512.f) - mean*mean;
  float rs = rsqrtf(var + 1e-5f);
  #pragma unroll
  for (int i = 0; i < 4; i++) {
    int d = t + i*128;
    float y = (v[i] - mean)*rs*(1.f + mr[d]) + mr[DIM + d];
    store_split((size_t)row*DIM + d, y);
  }
}

// ---------------- pipelined split-bf16 tensor-core GEMM -------------------
// A = g_xh/g_xl [M,K]; W = g_bh/g_bl + wOff [K,N]; C fp32 (out_sel).
#define BMT 128
#define BNT 64
#define BKT 32
#define NSTG 3
#define SA_STRIDE 40
#define SB_STRIDE 72
#define SA_SZ (BMT*SA_STRIDE)            // 5120 bf16
#define SB_SZ (BKT*SB_STRIDE)            // 2304 bf16
#define STAGE_ELEMS (2*SA_SZ + 2*SB_SZ)  // 14848 bf16
#define GEMM_SMEM (NSTG*STAGE_ELEMS*2)   // 89088 bytes

extern __shared__ __align__(16) __nv_bfloat16 dynsmem[];

__global__ void __launch_bounds__(256, 1)
gemm_mma(long wOff, const float* __restrict__ biasExt, int outSel, int qkvBlk,
         int M, int N, int K)
{
  const __nv_bfloat16* Ah = g_xh;
  const __nv_bfloat16* Al = g_xl;
  const __nv_bfloat16* Wh = g_bh + wOff;
  const __nv_bfloat16* Wl = g_bl + wOff;
  const float* bias = (qkvBlk >= 0) ? (g_bqkv + qkvBlk*QKV_N) : biasExt;
  float* C = out_sel(outSel);

  const int t = threadIdx.x, lane = t & 31, wid = t >> 5;
  const int wm = wid >> 1, wn = wid & 1;               // 4 x 2 warp grid
  const int bm = blockIdx.y * BMT, bn = blockIdx.x * BNT;
  const int NK = K / BKT;

  float acc[2][4][4];
  #pragma unroll
  for (int a = 0; a < 2; a++)
    #pragma unroll
    for (int b = 0; b < 4; b++)
      #pragma unroll
      for (int e = 0; e < 4; e++) acc[a][b][e] = 0.f;

  // async stage loader
  auto load_stage = [&](int st, int kt) {
    __nv_bfloat16* base = dynsmem + st*STAGE_ELEMS;
    __nv_bfloat16* sAh = base;
    __nv_bfloat16* sAl = base + SA_SZ;
    __nv_bfloat16* sBh = base + 2*SA_SZ;
    __nv_bfloat16* sBl = base + 2*SA_SZ + SB_SZ;
    const int k0 = kt*BKT;
    #pragma unroll
    for (int i = 0; i < 2; i++) {
      int u = t + i*256;
      int r = u >> 2, c8 = (u & 3) << 3;
      int gr = bm + r;
      bool ok = gr < M;
      size_t go = (size_t)(ok ? gr : 0)*K + k0 + c8;
      cp16(smem_u32(sAh + r*SA_STRIDE + c8), Ah + go, ok);
      cp16(smem_u32(sAl + r*SA_STRIDE + c8), Al + go, ok);
    }
    {
      int r = t >> 3, c8 = (t & 7) << 3;
      size_t go = (size_t)(k0 + r)*N + bn + c8;
      cp16(smem_u32(sBh + r*SB_STRIDE + c8), Wh + go, true);
      cp16(smem_u32(sBl + r*SB_STRIDE + c8), Wl + go, true);
    }
  };

  load_stage(0, 0); cp_commit();
  load_stage(1, 1); cp_commit();

  for (int kt = 0; kt < NK; kt++) {
    const int cur = kt % NSTG;
    if (kt + 2 < NK) load_stage((kt + 2) % NSTG, kt + 2);
    cp_commit();
    cp_wait<2>();
    __syncthreads();

    __nv_bfloat16* base = dynsmem + cur*STAGE_ELEMS;
    __nv_bfloat16* sAh = base;
    __nv_bfloat16* sAl = base + SA_SZ;
    __nv_bfloat16* sBh = base + 2*SA_SZ;
    __nv_bfloat16* sBl = base + 2*SA_SZ + SB_SZ;

    #pragma unroll
    for (int ks = 0; ks < BKT; ks += 16) {
      uint32_t ah[2][4], al[2][4], bh[4][2], bl[4][2];
      #pragma unroll
      for (int mg = 0; mg < 2; mg++) {
        int row = wm*32 + mg*16 + (lane & 15);
        int col = ks + ((lane >> 4) << 3);
        ldsm4(ah[mg], smem_u32(sAh + row*SA_STRIDE + col));
        ldsm4(al[mg], smem_u32(sAl + row*SA_STRIDE + col));
      }
      #pragma unroll
      for (int h2 = 0; h2 < 2; h2++) {
        int row = ks + (lane & 15);
        int col = wn*32 + h2*16 + ((lane >> 4) << 3);
        uint32_t r4[4];
        ldsm4t(r4, smem_u32(sBh + row*SB_STRIDE + col));
        bh[h2*2][0] = r4[0]; bh[h2*2][1] = r4[1];
        bh[h2*2+1][0] = r4[2]; bh[h2*2+1][1] = r4[3];
        ldsm4t(r4, smem_u32(sBl + row*SB_STRIDE + col));
        bl[h2*2][0] = r4[0]; bl[h2*2][1] = r4[1];
        bl[h2*2+1][0] = r4[2]; bl[h2*2+1][1] = r4[3];
      }
      #pragma unroll
      for (int mg = 0; mg < 2; mg++)
        #pragma unroll
        for (int ng = 0; ng < 4; ng++) {
          mma16816(acc[mg][ng], ah[mg], bh[ng]);
          mma16816(acc[mg][ng], ah[mg], bl[ng]);
          mma16816(acc[mg][ng], al[mg], bh[ng]);
        }
    }
    __syncthreads();
  }

  #pragma unroll
  for (int mg = 0; mg < 2; mg++) {
    int r0 = bm + wm*32 + mg*16 + (lane >> 2);
    #pragma unroll
    for (int ng = 0; ng < 4; ng++) {
      int cc = bn + wn*32 + ng*8 + ((lane & 3) << 1);
      float b0 = bias[cc], b1 = bias[cc+1];
      if (r0 < M) {
        float2 o = make_float2(acc[mg][ng][0] + b0, acc[mg][ng][1] + b1);
        *(float2*)(C + (size_t)r0*N + cc) = o;
      }
      int r1 = r0 + 8;
      if (r1 < M) {
        float2 o = make_float2(acc[mg][ng][2] + b0, acc[mg][ng][3] + b1);
        *(float2*)(C + (size_t)r1*N + cc) = o;
      }
    }
  }
}

// ---------------- flash attention over g_qkv; writes bf16 xh/xl -----------
// mode 0: cross (zr queries), mode 1: self (xa queries)
__global__ void __launch_bounds__(128, 1)
attn_kernel(int mode)
{
  const int tile = blockIdx.x, f = blockIdx.y, h = blockIdx.z;
  int qrow0, r0s, r0l, r1s, r1l;
  if (mode == 0) {
    qrow0 = f*SEQ + tile*128;
    r0s = f*SEQ; r0l = SEQ;
    int j0 = f - 4; if (j0 < 0) j0 = 0;
    r1s = LZR + j0*SEQ; r1l = (f - j0)*SEQ;
  } else {
    qrow0 = LZR + f*SEQ + tile*128;
    r0s = LZR; r0l = (f + 1)*SEQ;
    r1s = 0; r1l = 0;
  }
  int nq = SEQ - tile*128; if (nq > 128) nq = 128;
  const int t = threadIdx.x;
  const bool active = t < nq;
  const int qr = qrow0 + t;

  float q[64], o[64];
  #pragma unroll
  for (int d = 0; d < 64; d++) o[d] = 0.f;
  if (active) {
    const float4* qp = (const float4*)(g_qkv + (size_t)qr*QKV_N + h*DH);
    #pragma unroll
    for (int i = 0; i < 16; i++) {
      float4 v4 = qp[i];
      q[4*i+0] = v4.x*0.125f; q[4*i+1] = v4.y*0.125f;
      q[4*i+2] = v4.z*0.125f; q[4*i+3] = v4.w*0.125f;
    }
  }
  float m = -1e30f, l = 0.f;
  __shared__ float Ks[64][64];
  __shared__ float Vs[64][64];

  for (int r = 0; r < 2; r++) {
    const int ks = r ? r1s : r0s;
    const int kl = r ? r1l : r0l;
    for (int k0 = 0; k0 < kl; k0 += 64) {
      const int tl = min(64, kl - k0);
      __syncthreads();
      #pragma unroll
      for (int it = 0; it < 8; it++) {
        int idx = it*128 + t;
        int j = idx >> 4, d4 = (idx & 15) * 4;
        if (j < tl) {
          const float* kb = g_qkv + (size_t)(ks + k0 + j)*QKV_N + h*DH;
          *(float4*)&Ks[j][d4] = *(const float4*)(kb + DIM + d4);
          *(float4*)&Vs[j][d4] = *(const float4*)(kb + 2*DIM + d4);
        }
      }
      __syncthreads();
      if (active) {
        for (int j = 0; j < tl; j++) {
          float s = 0.f;
          #pragma unroll
          for (int d = 0; d < 64; d += 4) {
            float4 k4 = *(const float4*)&Ks[j][d];
            s += q[d]*k4.x + q[d+1]*k4.y + q[d+2]*k4.z + q[d+3]*k4.w;
          }
          float mn   = fmaxf(m, s);
          float corr = __expf(m - mn);
          float p    = __expf(s - mn);
          l = l*corr + p;
          if (corr != 1.f) {
            #pragma unroll
            for (int d = 0; d < 64; d++) o[d] *= corr;
          }
          m = mn;
          #pragma unroll
          for (int d = 0; d < 64; d += 4) {
            float4 v4 = *(const float4*)&Vs[j][d];
            o[d] += p*v4.x; o[d+1] += p*v4.y; o[d+2] += p*v4.z; o[d+3] += p*v4.w;
          }
        }
      }
    }
  }
  if (active) {
    float inv = 1.f / l;
    size_t base = (size_t)qr*DIM + h*DH;
    #pragma unroll
    for (int d = 0; d < 64; d++) store_split(base + d, o[d]*inv);
  }
}

// ---------------- geglu: xh/xl = split(a * gelu(g)) ----------------
__global__ void geglu_act()
{
  int idx = blockIdx.x*256 + threadIdx.x;
  if (idx >= LT*HIDN) return;
  int row = idx / HIDN, j = idx - row*HIDN;
  float a = g_u[(size_t)row*2*HIDN + j];
  float g = g_u[(size_t)row*2*HIDN + HIDN + j];
  float ge = 0.5f * g * (1.f + erff(g * 0.70710678118654752f));
  store_split((size_t)idx, a * ge);
}

// ---------------- gate2: g_act = g_cat * g2[slot] ----------------
__global__ void gate2k(int blk)
{
  int idx = blockIdx.x*256 + threadIdx.x;
  if (idx >= LT*DIM) return;
  int row = idx / DIM, d = idx - row*DIM;
  int slot = (row < LZR) ? row/SEQ : 6;
  g_act[idx] = g_cat[idx] * g_gt2[(blk*7 + slot)*DIM + d];
}

// ---------------- unpatch: out[1,6,3,32,32] ----------------
__global__ void unpatch(const float* __restrict__ Wu, const float* __restrict__ bu,
                        float* __restrict__ out)
{
  int e = blockIdx.x*128 + threadIdx.x;
  if (e >= DZR*3*32*32) return;
  int f   = e / (3*32*32);
  int rem = e - f*3*32*32;
  int c = rem >> 10;
  int y = (rem >> 5) & 31;
  int x = rem & 31;
  int row = f*SEQ + (y >> 1)*16 + (x >> 1);
  int k = c*4 + (y & 1)*2 + (x & 1);
  float s = bu[k];
  const float* a = g_act + (size_t)row*DIM;
  for (int d = 0; d < DIM; d++) s += a[d]*Wu[d*12 + k];
  out[e] = s;
}

// ---------------- launch ----------------
extern "C" void kernel_launch(void* const* d_in, const int* in_sizes, int n_in,
                              void* d_out, int out_size)
{
  const float* z        = (const float*)d_in[0];
  const float* frames   = (const float*)d_in[1];
  const int*   actions  = (const int*)  d_in[2];
  const int*   ts       = (const int*)  d_in[3];
  const float* Wp       = (const float*)d_in[4];
  const float* bp       = (const float*)d_in[5];
  const float* Wu       = (const float*)d_in[6];
  const float* bu       = (const float*)d_in[7];
  const float* regs     = (const float*)d_in[8];
  const float* pe       = (const float*)d_in[9];
  const float* aemb     = (const float*)d_in[10];
  const float* temb     = (const float*)d_in[11];
  const float* Wm1      = (const float*)d_in[12];
  const float* bm1      = (const float*)d_in[13];
  const float* Wm2      = (const float*)d_in[14];
  const float* bm2      = (const float*)d_in[15];
  const float* Wq       = (const float*)d_in[16];
  const float* bq       = (const float*)d_in[17];
  const float* Wk       = (const float*)d_in[18];
  const float* bk       = (const float*)d_in[19];
  const float* Wv       = (const float*)d_in[20];
  const float* bv       = (const float*)d_in[21];
  const float* Wo       = (const float*)d_in[22];
  const float* bo       = (const float*)d_in[23];
  const float* Wg1      = (const float*)d_in[24];
  const float* bg1      = (const float*)d_in[25];
  const float* Wg2      = (const float*)d_in[26];
  const float* bg2      = (const float*)d_in[27];
  const float* Wgeglu   = (const float*)d_in[28];
  const float* bgeglu   = (const float*)d_in[29];
  const float* Wff      = (const float*)d_in[30];
  const float* bff      = (const float*)d_in[31];

  cudaFuncSetAttribute(gemm_mma, cudaFuncAttributeMaxDynamicSharedMemorySize, GEMM_SMEM);

  const int MT = (LT + BMT - 1) / BMT;   // 23 M-tiles

  build_tokens<<<LT, 128>>>(z, frames, actions, Wp, bp, regs, pe, aemb);
  precompute_cond2<<<dim3(12, NBLK), 256>>>(ts, temb, Wm1, bm1, Wm2, bm2, Wg1, bg1, Wg2, bg2);

  // one-time weight splits (inside graph)
  split_w_qkv<<<(SZ_QKV + 255)/256, 256>>>(Wq, Wk, Wv);
  pack_bqkv<<<(NBLK*QKV_N + 255)/256, 256>>>(bq, bk, bv);
  split_w<<<(SZ_O + 255)/256, 256>>>(Wo, OFF_O, SZ_O);
  split_w<<<(SZ_GEGLU + 255)/256, 256>>>(Wgeglu, OFF_GEGLU, SZ_GEGLU);
  split_w<<<(SZ_FF + 255)/256, 256>>>(Wff, OFF_FF, SZ_FF);

  for (int i = 0; i < NBLK; i++) {
    row_mod<<<LT, 128>>>(i);                                       // g_cat + xh/xl
    gemm_mma<<<dim3(QKV_N/BNT, MT), 256, GEMM_SMEM>>>(
        OFF_QKV + (long)i*DIM*QKV_N, (const float*)nullptr, 0, i, LT, QKV_N, DIM);
    attn_kernel<<<dim3(3, DZR, NHEAD), 128>>>(0);                  // -> xh/xl
    attn_kernel<<<dim3(3, DXA, NHEAD), 128>>>(1);
    gemm_mma<<<dim3(DIM/BNT, MT), 256, GEMM_SMEM>>>(
        OFF_O + (long)i*DIM*DIM, bo + i*DIM, 1, -1, LT, DIM, DIM); // -> g_u
    gate_add_mod<<<LT, 128>>>(i);                                  // -> xh/xl
    gemm_mma<<<dim3(2*HIDN/BNT, MT), 256, GEMM_SMEM>>>(
        OFF_GEGLU + (long)i*DIM*2*HIDN, bgeglu + i*2*HIDN, 1, -1, LT, 2*HIDN, DIM); // -> g_u
    geglu_act<<<(LT*HIDN + 255)/256, 256>>>();                     // -> xh/xl
    gemm_mma<<<dim3(DIM/BNT, MT), 256, GEMM_SMEM>>>(
        OFF_FF + (long)i*HIDN*DIM, bff + i*DIM, 2, -1, LT, DIM, HIDN); // -> g_cat
    gate2k<<<(LT*DIM + 255)/256, 256>>>(i);
  }

  unpatch<<<(DZR*3*32*32 + 127)/128, 128>>>(Wu, bu, (float*)d_out);
}